// round 1
// baseline (speedup 1.0000x reference)
#include <cuda_runtime.h>

#define KA    9
#define HH    240
#define WW    240
#define HW    57600          // HH*WW
#define NTOT  518400         // KA*HW
#define WK    2160           // WW*KA
#define PRE   6000
#define POST  300
#define CAP   8192
#define NB    65536

__device__ unsigned            g_keys[NTOT];
__device__ unsigned            g_hist[NB];
__device__ unsigned            g_cnt;
__device__ int                 g_bound;
__device__ unsigned long long  g_cand[CAP];
__device__ int                 g_order[PRE];
__device__ float               g_sc[PRE];

__device__ __forceinline__ unsigned mono(float f) {
    unsigned b = __float_as_uint(f);
    return (b & 0x80000000u) ? ~b : (b | 0x80000000u);
}
__device__ __forceinline__ float unmono(unsigned m) {
    unsigned b = (m & 0x80000000u) ? (m ^ 0x80000000u) : ~m;
    return __uint_as_float(b);
}

// ---------------------------------------------------------------- zero hist
__global__ void k_zero() {
    int i = blockIdx.x * blockDim.x + threadIdx.x;
    if (i < NB) g_hist[i] = 0u;
    if (i == 0) g_cnt = 0u;
}

// ------------------------------------------- scores -> monotone keys + hist
__global__ void k_score(const float* __restrict__ cls) {
    int i = blockIdx.x * blockDim.x + threadIdx.x;
    if (i >= NTOT) return;
    int k = i / HW;
    int r = i - k * HW;
    float s = cls[(2 * k) * HW + r];        // even (positive-class) channel
    unsigned key = mono(s);
    g_keys[i] = key;
    atomicAdd(&g_hist[key >> 16], 1u);
}

// ------------------------------------- find boundary bucket of rank PRE
__global__ void k_bound() {
    __shared__ int ps[1024];
    int t = threadIdx.x;
    int base = t * 64;
    int sum = 0;
    #pragma unroll 8
    for (int j = 0; j < 64; ++j) sum += (int)g_hist[base + j];
    ps[t] = sum;
    __syncthreads();
    // inclusive suffix-scan (Hillis-Steele)
    for (int d = 1; d < 1024; d <<= 1) {
        int v = (t + d < 1024) ? ps[t + d] : 0;
        __syncthreads();
        ps[t] += v;
        __syncthreads();
    }
    int St  = ps[t];
    int St1 = (t + 1 < 1024) ? ps[t + 1] : 0;
    if (St >= PRE && St1 < PRE) {
        int running = St1;
        int B = base;
        for (int j = 63; j >= 0; --j) {
            running += (int)g_hist[base + j];
            if (running >= PRE) { B = base + j; break; }
        }
        g_bound = B;
    }
}

// ----------------------------------------------- compact candidates >= bound
__global__ void k_compact() {
    int i = blockIdx.x * blockDim.x + threadIdx.x;
    if (i >= NTOT) return;
    unsigned key = g_keys[i];
    if ((int)(key >> 16) >= g_bound) {
        unsigned pos = atomicAdd(&g_cnt, 1u);
        if (pos < CAP)
            g_cand[pos] = ((unsigned long long)key << 32) | (unsigned)(~(unsigned)i);
    }
}

// -------------------------------- one-block bitonic sort (desc) of 8192 u64
__global__ void k_sort() {
    extern __shared__ unsigned long long a[];
    int tid = threadIdx.x;
    int n = (int)min(g_cnt, (unsigned)CAP);
    for (int e = tid; e < CAP; e += blockDim.x)
        a[e] = (e < n) ? g_cand[e] : 0ULL;
    __syncthreads();
    for (int k = 2; k <= CAP; k <<= 1) {
        for (int j = k >> 1; j > 0; j >>= 1) {
            for (int e = tid; e < CAP; e += blockDim.x) {
                int x = e ^ j;
                if (x > e) {
                    unsigned long long u = a[e], v = a[x];
                    bool desc = ((e & k) == 0);
                    if (desc ? (u < v) : (u > v)) { a[e] = v; a[x] = u; }
                }
            }
            __syncthreads();
        }
    }
    for (int p = tid; p < PRE; p += blockDim.x) {
        unsigned long long v = a[p];
        g_order[p] = (int)(~(unsigned)v);
        g_sc[p]    = unmono((unsigned)(v >> 32));
    }
}

// --------------------------------------------------- one-block NMS + output
#define SUP_OFF  96000          // PRE * sizeof(float4)
#define KEPT_OFF 102016
#define NMS_SMEM 103424

__global__ void k_nms(const float* __restrict__ deltas,
                      const float* __restrict__ anchors,
                      float* __restrict__ out) {
    extern __shared__ char sm[];
    float4*        bx   = (float4*)sm;
    unsigned char* sup  = (unsigned char*)(sm + SUP_OFF);
    int*           kept = (int*)(sm + KEPT_OFF);
    int tid = threadIdx.x;

    // gather clipped boxes through the scrambled (torch-faithful) layout
    for (int p = tid; p < PRE; p += blockDim.x) {
        int i  = g_order[p];
        int hp = i / WK;
        int t  = i - hp * WK;
        int wp = t / KA;
        int kp = t - wp * KA;
        float v[4];
        #pragma unroll
        for (int j = 0; j < 4; ++j) {
            int F   = ((kp * 4 + j) * HH + hp) * WW + wp;
            int j2  = F & 3;
            int F4  = F >> 2;
            int k2  = F4 % KA;
            int rem = F4 / KA;
            int w2  = rem % WW;
            int h2  = rem / WW;
            float a = anchors[((h2 * WW + w2) * KA + k2) * 4 + j2];
            float d = deltas[(k2 * 4 + j2) * HW + h2 * WW + w2];
            v[j] = fminf(fmaxf(a + d, 0.0f), 1920.0f);
        }
        bx[p]  = make_float4(v[0], v[1], v[2], v[3]);
        sup[p] = 0;
    }
    __syncthreads();

    // serial greedy NMS with parallel suppression, early-exit at POST kept
    int nk = 0;
    int i  = 0;
    while (true) {
        while (i < PRE && sup[i]) ++i;     // uniform scan, data stable since last sync
        if (i >= PRE) break;
        if (tid == 0) kept[nk] = i;
        ++nk;
        if (nk >= POST) break;
        float4 bi = bx[i];
        float aw = fmaxf(bi.z - bi.x, 0.0f);
        float ah = fmaxf(bi.w - bi.y, 0.0f);
        float area_i = __fmul_rn(aw, ah);
        for (int j = i + 1 + tid; j < PRE; j += blockDim.x) {
            if (!sup[j]) {
                float4 bj = bx[j];
                float lx = fmaxf(bi.x, bj.x);
                float ly = fmaxf(bi.y, bj.y);
                float rx = fminf(bi.z, bj.z);
                float ry = fminf(bi.w, bj.w);
                float iw = fmaxf(rx - lx, 0.0f);
                float ih = fmaxf(ry - ly, 0.0f);
                float inter  = __fmul_rn(iw, ih);
                float bw = fmaxf(bj.z - bj.x, 0.0f);
                float bh = fmaxf(bj.w - bj.y, 0.0f);
                float area_j = __fmul_rn(bw, bh);
                float uni = fmaxf(__fsub_rn(__fadd_rn(area_i, area_j), inter), 1e-9f);
                if (__fdiv_rn(inter, uni) > 0.6f) sup[j] = 1;
            }
        }
        ++i;
        __syncthreads();
    }
    __syncthreads();

    // output [1, POST, 5]; nonzero(..., fill_value=0) -> pad with proposal 0
    for (int p = tid; p < POST; p += blockDim.x) {
        int q = (p < nk) ? kept[p] : 0;
        float4 b = bx[q];
        out[p * 5 + 0] = g_sc[q];
        out[p * 5 + 1] = b.x;
        out[p * 5 + 2] = b.y;
        out[p * 5 + 3] = b.z;
        out[p * 5 + 4] = b.w;
    }
}

// ---------------------------------------------------------------- launcher
extern "C" void kernel_launch(void* const* d_in, const int* in_sizes, int n_in,
                              void* d_out, int out_size) {
    const float* cls     = (const float*)d_in[0];  // [1, 2K, H, W]
    const float* deltas  = (const float*)d_in[1];  // [1, 4K, H, W]
    const float* anchors = (const float*)d_in[2];  // [H, W, K, 4]
    float* out = (float*)d_out;                    // [1, POST, 5]

    cudaFuncSetAttribute(k_sort, cudaFuncAttributeMaxDynamicSharedMemorySize, CAP * 8);
    cudaFuncSetAttribute(k_nms,  cudaFuncAttributeMaxDynamicSharedMemorySize, NMS_SMEM);

    k_zero   <<<(NB   + 255) / 256, 256>>>();
    k_score  <<<(NTOT + 255) / 256, 256>>>(cls);
    k_bound  <<<1, 1024>>>();
    k_compact<<<(NTOT + 255) / 256, 256>>>();
    k_sort   <<<1, 1024, CAP * 8>>>();
    k_nms    <<<1, 1024, NMS_SMEM>>>(deltas, anchors, out);
}

// round 2
// speedup vs baseline: 1.0209x; 1.0209x over previous
#include <cuda_runtime.h>
#include <cub/cub.cuh>

#define KA    9
#define HH    240
#define WW    240
#define HW    57600          // HH*WW
#define NTOT  518400         // KA*HW
#define WK    2160           // WW*KA
#define PRE   6000
#define POST  300
#define CAP   8192
#define NB    65536
#define WORDS 188            // ceil(PRE/32)

__device__ unsigned            g_keys[NTOT];
__device__ unsigned            g_hist[NB];
__device__ unsigned            g_cnt;
__device__ int                 g_bound;
__device__ unsigned long long  g_cand[CAP];
__device__ int                 g_order[PRE];
__device__ float               g_sc[PRE];
__device__ float4              g_boxes[PRE];

__device__ __forceinline__ unsigned mono(float f) {
    unsigned b = __float_as_uint(f);
    return (b & 0x80000000u) ? ~b : (b | 0x80000000u);
}
__device__ __forceinline__ float unmono(unsigned m) {
    unsigned b = (m & 0x80000000u) ? (m ^ 0x80000000u) : ~m;
    return __uint_as_float(b);
}

// ---------------------------------------------------------------- zero hist
__global__ void k_zero() {
    int i = blockIdx.x * blockDim.x + threadIdx.x;
    if (i < NB) g_hist[i] = 0u;
    if (i == 0) g_cnt = 0u;
}

// ------------------------------------------- scores -> monotone keys + hist
__global__ void k_score(const float* __restrict__ cls) {
    int i = blockIdx.x * blockDim.x + threadIdx.x;
    if (i >= NTOT) return;
    int k = i / HW;
    int r = i - k * HW;
    float s = cls[(2 * k) * HW + r];        // even (positive-class) channel
    unsigned key = mono(s);
    g_keys[i] = key;
    atomicAdd(&g_hist[key >> 16], 1u);
}

// ------------------------------------- find boundary bucket of rank PRE
__global__ void k_bound() {
    __shared__ int ps[1024];
    int t = threadIdx.x;
    int base = t * 64;
    int sum = 0;
    #pragma unroll 8
    for (int j = 0; j < 64; ++j) sum += (int)g_hist[base + j];
    ps[t] = sum;
    __syncthreads();
    for (int d = 1; d < 1024; d <<= 1) {
        int v = (t + d < 1024) ? ps[t + d] : 0;
        __syncthreads();
        ps[t] += v;
        __syncthreads();
    }
    int St  = ps[t];
    int St1 = (t + 1 < 1024) ? ps[t + 1] : 0;
    if (St >= PRE && St1 < PRE) {
        int running = St1;
        int B = base;
        for (int j = 63; j >= 0; --j) {
            running += (int)g_hist[base + j];
            if (running >= PRE) { B = base + j; break; }
        }
        g_bound = B;
    }
}

// ----------------------------------------------- compact candidates >= bound
__global__ void k_compact() {
    int i = blockIdx.x * blockDim.x + threadIdx.x;
    if (i >= NTOT) return;
    unsigned key = g_keys[i];
    if ((int)(key >> 16) >= g_bound) {
        unsigned pos = atomicAdd(&g_cnt, 1u);
        if (pos < CAP)
            g_cand[pos] = ((unsigned long long)key << 20)
                        | (unsigned)((~(unsigned)i) & 0xFFFFFu);
    }
}

// ---------------------------- one-block cub radix sort (desc, 52-bit keys)
typedef cub::BlockRadixSort<unsigned long long, 1024, 8> Sorter;

__global__ __launch_bounds__(1024) void k_sort() {
    extern __shared__ char smraw[];
    Sorter::TempStorage& ts = *reinterpret_cast<Sorter::TempStorage*>(smraw);
    unsigned n = g_cnt;
    if (n > CAP) n = CAP;
    unsigned long long keys[8];
    #pragma unroll
    for (int it = 0; it < 8; ++it) {
        int e = threadIdx.x * 8 + it;
        keys[it] = (e < (int)n) ? g_cand[e] : 0ULL;
    }
    Sorter(ts).SortDescending(keys, 0, 52);
    #pragma unroll
    for (int it = 0; it < 8; ++it) {
        int p = threadIdx.x * 8 + it;
        if (p < PRE) {
            unsigned long long v = keys[it];
            g_order[p] = (int)((~(unsigned)v) & 0xFFFFFu);
            g_sc[p]    = unmono((unsigned)(v >> 20));
        }
    }
}

// --------------------------- grid-wide gather of clipped boxes (torch layout)
__global__ void k_gather(const float* __restrict__ deltas,
                         const float* __restrict__ anchors) {
    int p = blockIdx.x * blockDim.x + threadIdx.x;
    if (p >= PRE) return;
    int i  = g_order[p];
    int hp = i / WK;
    int t  = i - hp * WK;
    int wp = t / KA;
    int kp = t - wp * KA;
    float v[4];
    #pragma unroll
    for (int j = 0; j < 4; ++j) {
        int F   = ((kp * 4 + j) * HH + hp) * WW + wp;
        int j2  = F & 3;
        int F4  = F >> 2;
        int k2  = F4 % KA;
        int rem = F4 / KA;
        int w2  = rem % WW;
        int h2  = rem / WW;
        float a = anchors[((h2 * WW + w2) * KA + k2) * 4 + j2];
        float d = deltas[(k2 * 4 + j2) * HW + h2 * WW + w2];
        v[j] = fminf(fmaxf(a + d, 0.0f), 1920.0f);
    }
    g_boxes[p] = make_float4(v[0], v[1], v[2], v[3]);
}

// --------------------------------------------------- one-block NMS + output
__global__ __launch_bounds__(1024) void k_nms(float* __restrict__ out) {
    extern __shared__ float4 bx[];            // PRE * 16 bytes
    __shared__ unsigned supw[WORDS];
    __shared__ int kept[POST];
    int tid  = threadIdx.x;
    int warp = tid >> 5, lane = tid & 31;

    for (int p = tid; p < PRE; p += 1024) bx[p] = g_boxes[p];
    if (tid < WORDS) supw[tid] = (tid == WORDS - 1) ? 0xFFFF0000u : 0u;  // pad bits >= PRE
    __syncthreads();

    int nk = 0, i = 0;
    while (true) {
        // find next unsuppressed index >= i (uniform across block; smem broadcast)
        int wi = i >> 5;
        unsigned w = supw[wi] | ((1u << (i & 31)) - 1u);
        while (w == 0xFFFFFFFFu && ++wi < WORDS) w = supw[wi];
        if (w == 0xFFFFFFFFu) break;          // exhausted
        i = (wi << 5) + (__ffs(~w) - 1);
        if (tid == 0) kept[nk] = i;
        ++nk;
        if (nk >= POST) break;

        float4 bi = bx[i];
        float aw = fmaxf(bi.z - bi.x, 0.0f);
        float ah = fmaxf(bi.w - bi.y, 0.0f);
        float area_i = __fmul_rn(aw, ah);

        int w0 = (i + 1) >> 5;
        for (int wd = w0 + warp; wd < WORDS; wd += 32) {
            unsigned cur = supw[wd];
            if (cur != 0xFFFFFFFFu) {
                int j = (wd << 5) + lane;
                bool sup = false;
                if (j > i && !((cur >> lane) & 1u)) {   // bits >= PRE pre-set -> never enters
                    float4 bj = bx[j];
                    float lx = fmaxf(bi.x, bj.x);
                    float ly = fmaxf(bi.y, bj.y);
                    float rx = fminf(bi.z, bj.z);
                    float ry = fminf(bi.w, bj.w);
                    float iw = fmaxf(rx - lx, 0.0f);
                    float ih = fmaxf(ry - ly, 0.0f);
                    float inter  = __fmul_rn(iw, ih);
                    float bw = fmaxf(bj.z - bj.x, 0.0f);
                    float bh = fmaxf(bj.w - bj.y, 0.0f);
                    float area_j = __fmul_rn(bw, bh);
                    float uni = fmaxf(__fsub_rn(__fadd_rn(area_i, area_j), inter), 1e-9f);
                    sup = (__fdiv_rn(inter, uni) > 0.6f);
                }
                unsigned nb = __ballot_sync(0xFFFFFFFFu, sup);
                if (lane == 0 && nb) supw[wd] = cur | nb;   // exclusive word ownership
            }
        }
        ++i;
        __syncthreads();
    }
    __syncthreads();

    // output [1, POST, 5]; nonzero(..., fill_value=0) -> pad with proposal 0
    for (int p = tid; p < POST; p += 1024) {
        int q = (p < nk) ? kept[p] : 0;
        float4 b = bx[q];
        out[p * 5 + 0] = g_sc[q];
        out[p * 5 + 1] = b.x;
        out[p * 5 + 2] = b.y;
        out[p * 5 + 3] = b.z;
        out[p * 5 + 4] = b.w;
    }
}

// ---------------------------------------------------------------- launcher
extern "C" void kernel_launch(void* const* d_in, const int* in_sizes, int n_in,
                              void* d_out, int out_size) {
    const float* cls     = (const float*)d_in[0];  // [1, 2K, H, W]
    const float* deltas  = (const float*)d_in[1];  // [1, 4K, H, W]
    const float* anchors = (const float*)d_in[2];  // [H, W, K, 4]
    float* out = (float*)d_out;                    // [1, POST, 5]

    cudaFuncSetAttribute(k_sort, cudaFuncAttributeMaxDynamicSharedMemorySize,
                         (int)sizeof(Sorter::TempStorage));
    cudaFuncSetAttribute(k_nms,  cudaFuncAttributeMaxDynamicSharedMemorySize,
                         PRE * (int)sizeof(float4));

    k_zero   <<<(NB   + 255) / 256, 256>>>();
    k_score  <<<(NTOT + 255) / 256, 256>>>(cls);
    k_bound  <<<1, 1024>>>();
    k_compact<<<(NTOT + 255) / 256, 256>>>();
    k_sort   <<<1, 1024, sizeof(Sorter::TempStorage)>>>();
    k_gather <<<(PRE + 255) / 256, 256>>>(deltas, anchors);
    k_nms    <<<1, 1024, PRE * sizeof(float4)>>>(out);
}